// round 15
// baseline (speedup 1.0000x reference)
#include <cuda_runtime.h>
#include <cuda_fp16.h>
#include <cstdint>

#define B_ 4
#define C_ 32
#define H_ 1024
#define W_ 64
#define BW_ 256
// SCALE * log2(e): exp(s) computed as ex2(s') with scale folded into Q
#define PSCALE 0.12753139766698305f

// Scratch (__device__ globals; allocations forbidden). fp16 (calibrated R4-R14).
__device__ __half g_Q[BW_ * H_ * C_];   // [bw][h][c], pre-scaled by PSCALE
__device__ __half g_K[BW_ * H_ * C_];
__device__ __half g_V[BW_ * H_ * C_];
__device__ float  g_O[BW_ * H_ * C_];   // [bw][h][c] fp32

// ---------------------------------------------------------------------------
// helpers
// ---------------------------------------------------------------------------
__device__ __forceinline__ uint32_t smem_u32(const void* p) {
    uint32_t a;
    asm("{ .reg .u64 t; cvta.to.shared.u64 t, %1; cvt.u32.u64 %0, t; }" : "=r"(a) : "l"(p));
    return a;
}
__device__ __forceinline__ uint32_t lds32(uint32_t a) {
    uint32_t v;
    asm volatile("ld.shared.b32 %0, [%1];" : "=r"(v) : "r"(a));
    return v;
}
// pack two fp32 -> f16x2, e0 low half, e1 high half
__device__ __forceinline__ uint32_t pk(float e0, float e1) {
    uint32_t r;
    asm("cvt.rn.f16x2.f32 %0, %1, %2;" : "=r"(r) : "f"(e1), "f"(e0));
    return r;
}
// packed fp16x2 2^x (one MUFU op for two elements)
__device__ __forceinline__ uint32_t ex2h2(uint32_t x) {
    uint32_t r;
    asm("ex2.approx.f16x2 %0, %1;" : "=r"(r) : "r"(x));
    return r;
}

#define MMA16816(d, a0, a1, a2, a3, b0, b1)                                    \
    asm volatile("mma.sync.aligned.m16n8k16.row.col.f32.f16.f16.f32 "          \
        "{%0,%1,%2,%3}, {%4,%5,%6,%7}, {%8,%9}, {%0,%1,%2,%3};"                \
        : "+f"((d)[0]), "+f"((d)[1]), "+f"((d)[2]), "+f"((d)[3])               \
        : "r"(a0), "r"(a1), "r"(a2), "r"(a3), "r"(b0), "r"(b1))

#define LDMX4T(r0, r1, r2, r3, addr)                                           \
    asm volatile("ldmatrix.sync.aligned.m8n8.x4.trans.shared.b16 {%0,%1,%2,%3}, [%4];" \
        : "=r"(r0), "=r"(r1), "=r"(r2), "=r"(r3) : "r"(addr))

#define LDMX4(r0, r1, r2, r3, addr)                                            \
    asm volatile("ldmatrix.sync.aligned.m8n8.x4.shared.b16 {%0,%1,%2,%3}, [%4];" \
        : "=r"(r0), "=r"(r1), "=r"(r2), "=r"(r3) : "r"(addr))

#define CP16(dst, src)                                                         \
    asm volatile("cp.async.cg.shared.global [%0], [%1], 16;" :: "r"(dst), "l"(src))
#define CP_COMMIT() asm volatile("cp.async.commit_group;")
#define CP_WAIT(n)  asm volatile("cp.async.wait_group %0;" :: "n"(n))

// ---------------------------------------------------------------------------
// Kernel 1: tensor-core QKV projection; 2 h-tiles per CTA (W staged once).
// Per tile: A = x rows [(2h x 64w) = 128 rows x 32c] (fp16 hi/lo, 2-pass),
// B = stacked [Wq*PSCALE; Wk; Wv] [96 x 32] fp16.
// grid (256 htiles, 4 b), 256 threads (8 warps x 16 rows).
// ---------------------------------------------------------------------------
#define PXH 0
#define PXL 10240
#define PW  20480
#define PBI 28160
#define PST 0        // output stage overlays PXH/PXL after MMAs (64 w x 272B)
__global__ void __launch_bounds__(256) proj_tc(
    const float* __restrict__ x,
    const float* __restrict__ wq, const float* __restrict__ bq,
    const float* __restrict__ wk, const float* __restrict__ bk,
    const float* __restrict__ wv, const float* __restrict__ bv)
{
    __shared__ __align__(16) char sm[28544];
    const uint32_t sbase = smem_u32(sm);

    const int t = threadIdx.x;
    const int lane = t & 31, warp = t >> 5;
    const int b = blockIdx.y;

    // ---- W -> smem ONCE; [o][c] fp16, rows 80B pitch; o: q 0-31, k 32-63, v 64-95
    for (int i = t; i < 3072; i += 256) {
        const int o = i >> 5, c = i & 31;
        float v = (o < 32) ? wq[o * 32 + c] * PSCALE
                : (o < 64) ? wk[(o - 32) * 32 + c]
                           : wv[(o - 64) * 32 + c];
        *(__half*)(sm + PW + o * 80 + c * 2) = __float2half_rn(v);
    }
    if (t < 96) {
        float v = (t < 32) ? bq[t] * PSCALE : (t < 64) ? bk[t - 32] : bv[t - 64];
        *(float*)(sm + PBI + t * 4) = v;
    }

    const int qrow = lane >> 2;
    const int lc4 = (lane & 3) * 4;
    const int wr = warp * 16;
    const uint32_t wmoff = (lane & 7) * 80 + ((lane >> 3) & 1) * 16 + (lane >> 4) * 32;
    const int r = t & 127;                 // staging: fixed row per thread
    const int cbase = (t >> 7) * 16;       // 0 or 16

    #pragma unroll 1
    for (int it = 0; it < 2; it++) {
        const int h0 = blockIdx.x * 4 + it * 2;
        if (it) __syncthreads();   // prev writeout's PST reads done before restage

        // ---- x -> smem hi/lo [r][c]; hi/lo pairs packed into u32 stores ----
        {
            const float* xr = x + ((size_t)(b * 32) * 1024 + h0 + (r >> 6)) * 64 + (r & 63);
            const uint32_t sh = sbase + PXH + r * 80 + cbase * 2;
            const uint32_t sl = sbase + PXL + r * 80 + cbase * 2;
            #pragma unroll
            for (int k = 0; k < 8; k++) {
                const float f0 = xr[(size_t)(cbase + 2 * k) * 65536];
                const float f1 = xr[(size_t)(cbase + 2 * k + 1) * 65536];
                const float h0f = __half2float(__float2half_rn(f0));
                const float h1f = __half2float(__float2half_rn(f1));
                asm volatile("st.shared.b32 [%0], %1;" :: "r"(sh + k * 4), "r"(pk(h0f, h1f)));
                asm volatile("st.shared.b32 [%0], %1;" :: "r"(sl + k * 4),
                    "r"(pk(f0 - h0f, f1 - h1f)));
            }
        }
        __syncthreads();

        // ---- GEMM: 12 n-tiles x (1 LDMX4 + 4 MMA) = 48 MMA/warp ----
        uint32_t xh[8], xl[8];
        #pragma unroll
        for (int ks = 0; ks < 2; ks++) {
            const uint32_t aq = sbase + PXH + (wr + qrow) * 80 + lc4 + ks * 32;
            xh[ks * 4 + 0] = lds32(aq);          xh[ks * 4 + 1] = lds32(aq + 640);
            xh[ks * 4 + 2] = lds32(aq + 16);     xh[ks * 4 + 3] = lds32(aq + 656);
            xl[ks * 4 + 0] = lds32(aq + 10240);  xl[ks * 4 + 1] = lds32(aq + 10880);
            xl[ks * 4 + 2] = lds32(aq + 10256);  xl[ks * 4 + 3] = lds32(aq + 10896);
        }

        float acc[12][4];
        #pragma unroll
        for (int nt = 0; nt < 12; nt++) {
            acc[nt][0] = 0.f; acc[nt][1] = 0.f; acc[nt][2] = 0.f; acc[nt][3] = 0.f;
            uint32_t b0, b1, b2, b3;
            LDMX4(b0, b1, b2, b3, sbase + PW + wmoff + nt * 640);
            MMA16816(acc[nt], xh[0], xh[1], xh[2], xh[3], b0, b1);
            MMA16816(acc[nt], xl[0], xl[1], xl[2], xl[3], b0, b1);
            MMA16816(acc[nt], xh[4], xh[5], xh[6], xh[7], b2, b3);
            MMA16816(acc[nt], xl[4], xl[5], xl[6], xl[7], b2, b3);
        }

        // ---- epilogue: per tensor, stage (272B-pitch rows: 2 hl x 64B),
        //      then 128B-contiguous writes per w ----
        const int r0 = wr + qrow, r1 = r0 + 8;
        const uint32_t st0 = sbase + PST + (r0 & 63) * 272 + (r0 >> 6) * 64;
        const uint32_t st1 = sbase + PST + (r1 & 63) * 272 + (r1 >> 6) * 64;
        #pragma unroll
        for (int tensor = 0; tensor < 3; tensor++) {
            __syncthreads();   // A-frag reads / prev writeout done
            #pragma unroll
            for (int j = 0; j < 4; j++) {
                const int nt = tensor * 4 + j;
                const int cb = j * 16 + (lane & 3) * 4;
                const float2 bi = *(const float2*)(sm + PBI + tensor * 128 + cb * 2);
                asm volatile("st.shared.b32 [%0], %1;" ::
                    "r"(st0 + cb), "r"(pk(acc[nt][0] + bi.x, acc[nt][1] + bi.y)));
                asm volatile("st.shared.b32 [%0], %1;" ::
                    "r"(st1 + cb), "r"(pk(acc[nt][2] + bi.x, acc[nt][3] + bi.y)));
            }
            __syncthreads();
            __half* g = (tensor == 0) ? g_Q : (tensor == 1) ? g_K : g_V;
            for (int i = t; i < 512; i += 256) {
                const int w = i >> 3, ch = i & 7;
                *(uint4*)((char*)(g + ((size_t)(b * 64 + w) * 1024 + h0) * 32) + ch * 16) =
                    *(const uint4*)(sm + PST + w * 272 + ch * 16);
            }
        }
    }
}

// ---------------------------------------------------------------------------
// Kernel 2: attention. S in two 8-n-tile halves (sacc[8][4], 3 CTAs/SM),
// cp.async triple-buffered K/V, rowsum via REGISTER ones fragment (no smem),
// exp via ex2.f16x2. grid (256, 8), block 256.
// ---------------------------------------------------------------------------
#define SQ    0
#define SKV0  10240
#define SKVSZ 20480
#define ATT_SMEM 71680   // Q 10K + 3 x (K 10K + V 10K); 3 CTAs = 215KB/SM

__global__ void __launch_bounds__(256, 3) att3_kernel(
    const float* __restrict__ w_lin, const float* __restrict__ b_lin)
{
    extern __shared__ char sm[];
    const uint32_t sbase = smem_u32(sm);

    const int t = threadIdx.x;
    const int lane = t & 31, warp = t >> 5;
    const int bw = blockIdx.x, qt = blockIdx.y;

    const int qrow = lane >> 2;
    const int lc4 = (lane & 3) * 4;
    const int wr = warp * 16;

    const size_t qbase = ((size_t)bw * H_ + (size_t)qt * 128) * 32;
    const size_t kvb = (size_t)bw * H_ * 32;

    // ones-column B fragment for the rowsum MMA, synthesized in registers:
    // B[k][n]=1 iff n==0 (local) -> lanes with n-group 0 (lane>>2==0) hold 1.0h pairs
    const uint32_t onesf = ((lane >> 2) == 0) ? 0x3C003C00u : 0u;

    // ---- group 0: Q tile + K/V tile 0 (buf 0) ----
    {
        const char* qg = (const char*)(g_Q + qbase);
        const char* kg = (const char*)(g_K + kvb);
        const char* vg = (const char*)(g_V + kvb);
        for (int i = t; i < 512; i += 256) {
            const uint32_t o = (i >> 2) * 80 + (i & 3) * 16;
            CP16(sbase + SQ + o, qg + i * 16);
            CP16(sbase + SKV0 + o, kg + i * 16);
            CP16(sbase + SKV0 + 10240 + o, vg + i * 16);
        }
        CP_COMMIT();
    }

    float sacc[8][4];
    float oacc[5][4];
    #pragma unroll
    for (int n = 0; n < 5; n++)
        #pragma unroll
        for (int e = 0; e < 4; e++) oacc[n][e] = 0.f;

    uint32_t qf[8];   // Q fragments, tile-invariant (loaded once at kt=0)
    // ldmatrix (non-trans) per-lane row address offset for K fragments
    const uint32_t kmoff = (lane & 7) * 80 + ((lane >> 3) & 1) * 16 + (lane >> 4) * 32;

    for (int kt = 0; kt < 8; kt++) {
        if (kt < 7) {   // prefetch next tile into buffer (kt+1)%3
            const char* kg = (const char*)(g_K + kvb + (size_t)(kt + 1) * 4096);
            const char* vg = (const char*)(g_V + kvb + (size_t)(kt + 1) * 4096);
            const uint32_t kb2 = sbase + SKV0 + ((kt + 1) % 3) * SKVSZ;
            for (int i = t; i < 512; i += 256) {
                const uint32_t o = (i >> 2) * 80 + (i & 3) * 16;
                CP16(kb2 + o, kg + i * 16);
                CP16(kb2 + 10240 + o, vg + i * 16);
            }
            CP_COMMIT();
            CP_WAIT(1);
        } else {
            CP_WAIT(0);
        }
        __syncthreads();   // tile kt visible to all warps

        if (kt == 0) {     // Q arrived with group 0 — load frags once
            #pragma unroll
            for (int ks = 0; ks < 2; ks++) {
                const uint32_t aq = sbase + SQ + (wr + qrow) * 80 + lc4 + ks * 32;
                qf[ks * 4 + 0] = lds32(aq);
                qf[ks * 4 + 1] = lds32(aq + 640);
                qf[ks * 4 + 2] = lds32(aq + 16);
                qf[ks * 4 + 3] = lds32(aq + 656);
            }
        }

        const uint32_t kb = sbase + SKV0 + (kt % 3) * SKVSZ;
        const uint32_t vb = kb + 10240;
        const uint32_t kmbase = kb + kmoff;

        // ---- two halves: S for 8 n-tiles, then PV for matching 4 ks ----
        #pragma unroll
        for (int half = 0; half < 2; half++) {
            #pragma unroll
            for (int j = 0; j < 8; j++) {
                sacc[j][0] = 0.f; sacc[j][1] = 0.f; sacc[j][2] = 0.f; sacc[j][3] = 0.f;
                uint32_t b0, b1, b2, b3;
                LDMX4(b0, b1, b2, b3, kmbase + (half * 8 + j) * 640);
                MMA16816(sacc[j], qf[0], qf[1], qf[2], qf[3], b0, b1);
                MMA16816(sacc[j], qf[4], qf[5], qf[6], qf[7], b2, b3);
            }
            #pragma unroll
            for (int k2 = 0; k2 < 4; k2++) {
                const int ks = half * 4 + k2;
                const float* p0 = sacc[2 * k2];
                const float* p1 = sacc[2 * k2 + 1];
                const uint32_t a0 = ex2h2(pk(p0[0], p0[1]));
                const uint32_t a1 = ex2h2(pk(p0[2], p0[3]));
                const uint32_t a2 = ex2h2(pk(p1[0], p1[1]));
                const uint32_t a3 = ex2h2(pk(p1[2], p1[3]));
                const uint32_t va4 = vb + (ks * 16 + (lane & 15)) * 80 + (lane >> 4) * 16;
                uint32_t v0, v1, v2, v3;
                LDMX4T(v0, v1, v2, v3, va4);          // n-tiles 0,1
                MMA16816(oacc[0], a0, a1, a2, a3, v0, v1);
                MMA16816(oacc[1], a0, a1, a2, a3, v2, v3);
                LDMX4T(v0, v1, v2, v3, va4 + 32);     // n-tiles 2,3
                MMA16816(oacc[2], a0, a1, a2, a3, v0, v1);
                MMA16816(oacc[3], a0, a1, a2, a3, v2, v3);
                MMA16816(oacc[4], a0, a1, a2, a3, onesf, onesf);  // rowsum
            }
        }
        // no trailing barrier: triple buffer guarantees prefetch (kt+1)%3
        // never aliases any buffer a laggard warp (at worst in compute kt) reads
    }

    // ---- finalize: rowsums live in oacc[4] col ch32 (lane&3==0) ----
    const float rs0 = __shfl_sync(0xffffffffu, oacc[4][0], lane & 28);
    const float rs1 = __shfl_sync(0xffffffffu, oacc[4][2], lane & 28);

    float ws = 0.f;
    #pragma unroll
    for (int k = 0; k < 8; k++) ws += w_lin[k];
    const float bb = b_lin[0];
    const float f0 = ws / rs0, f1 = ws / rs1;

    const int row = qt * 128 + wr + qrow;
    float* ob = g_O + ((size_t)bw * H_ + row) * 32 + (lane & 3) * 2;
    #pragma unroll
    for (int nt = 0; nt < 4; nt++) {
        float2 v0 = make_float2(oacc[nt][0] * f0 + bb, oacc[nt][1] * f0 + bb);
        float2 v1 = make_float2(oacc[nt][2] * f1 + bb, oacc[nt][3] * f1 + bb);
        *(float2*)(ob + nt * 8) = v0;
        *(float2*)(ob + 8 * 32 + nt * 8) = v1;
    }
}

// ---------------------------------------------------------------------------
// Kernel 3: epilogue transpose  g_O [bw][h][c] -> out [b][c][h][w]
// ---------------------------------------------------------------------------
__global__ void __launch_bounds__(256) transpose_kernel(float* __restrict__ out)
{
    __shared__ float tile[32][33];
    const int b = blockIdx.z, h = blockIdx.y, w0 = blockIdx.x * 32;

    for (int wi = threadIdx.y; wi < 32; wi += 8)
        tile[wi][threadIdx.x] = g_O[(((long)(b * 64 + w0 + wi)) * H_ + h) * 32 + threadIdx.x];
    __syncthreads();
    for (int c = threadIdx.y; c < 32; c += 8)
        out[(((long)(b * 32 + c)) * H_ + h) * 64 + w0 + threadIdx.x] = tile[threadIdx.x][c];
}

// ---------------------------------------------------------------------------
extern "C" void kernel_launch(void* const* d_in, const int* in_sizes, int n_in,
                              void* d_out, int out_size)
{
    const float* x  = (const float*)d_in[0];
    const float* wq = (const float*)d_in[1];
    const float* bq = (const float*)d_in[2];
    const float* wk = (const float*)d_in[3];
    const float* bk = (const float*)d_in[4];
    const float* wv = (const float*)d_in[5];
    const float* bv = (const float*)d_in[6];
    const float* wl = (const float*)d_in[7];
    const float* bl = (const float*)d_in[8];
    float* out = (float*)d_out;

    cudaFuncSetAttribute(att3_kernel, cudaFuncAttributeMaxDynamicSharedMemorySize, ATT_SMEM);

    proj_tc<<<dim3(256, 4), 256>>>(x, wq, bq, wk, bk, wv, bv);
    att3_kernel<<<dim3(256, 8), 256, ATT_SMEM>>>(wl, bl);
    transpose_kernel<<<dim3(2, 1024, 4), dim3(32, 8)>>>(out);
}

// round 17
// speedup vs baseline: 1.0462x; 1.0462x over previous
#include <cuda_runtime.h>
#include <cuda_fp16.h>
#include <cstdint>

#define B_ 4
#define C_ 32
#define H_ 1024
#define W_ 64
#define BW_ 256
// SCALE * log2(e): exp(s) computed as ex2(s') with scale folded into Q
#define PSCALE 0.12753139766698305f

// Scratch (__device__ globals; allocations forbidden). fp16 (calibrated R4-R15).
__device__ __half g_Q[BW_ * H_ * C_];   // [bw][h][c], pre-scaled by PSCALE
__device__ __half g_K[BW_ * H_ * C_];
__device__ __half g_V[BW_ * H_ * C_];
__device__ float  g_O[BW_ * H_ * C_];   // [bw][h][c] fp32

// ---------------------------------------------------------------------------
// helpers
// ---------------------------------------------------------------------------
__device__ __forceinline__ uint32_t smem_u32(const void* p) {
    uint32_t a;
    asm("{ .reg .u64 t; cvta.to.shared.u64 t, %1; cvt.u32.u64 %0, t; }" : "=r"(a) : "l"(p));
    return a;
}
__device__ __forceinline__ uint32_t lds32(uint32_t a) {
    uint32_t v;
    asm volatile("ld.shared.b32 %0, [%1];" : "=r"(v) : "r"(a));
    return v;
}
// pack two fp32 -> f16x2, e0 low half, e1 high half
__device__ __forceinline__ uint32_t pk(float e0, float e1) {
    uint32_t r;
    asm("cvt.rn.f16x2.f32 %0, %1, %2;" : "=r"(r) : "f"(e1), "f"(e0));
    return r;
}
// packed fp16x2 2^x (one MUFU op for two elements)
__device__ __forceinline__ uint32_t ex2h2(uint32_t x) {
    uint32_t r;
    asm("ex2.approx.f16x2 %0, %1;" : "=r"(r) : "r"(x));
    return r;
}

#define MMA16816(d, a0, a1, a2, a3, b0, b1)                                    \
    asm volatile("mma.sync.aligned.m16n8k16.row.col.f32.f16.f16.f32 "          \
        "{%0,%1,%2,%3}, {%4,%5,%6,%7}, {%8,%9}, {%0,%1,%2,%3};"                \
        : "+f"((d)[0]), "+f"((d)[1]), "+f"((d)[2]), "+f"((d)[3])               \
        : "r"(a0), "r"(a1), "r"(a2), "r"(a3), "r"(b0), "r"(b1))

#define LDMX2T(r0, r1, addr)                                                   \
    asm volatile("ldmatrix.sync.aligned.m8n8.x2.trans.shared.b16 {%0,%1}, [%2];" \
        : "=r"(r0), "=r"(r1) : "r"(addr))

#define LDMX4T(r0, r1, r2, r3, addr)                                           \
    asm volatile("ldmatrix.sync.aligned.m8n8.x4.trans.shared.b16 {%0,%1,%2,%3}, [%4];" \
        : "=r"(r0), "=r"(r1), "=r"(r2), "=r"(r3) : "r"(addr))

#define LDMX4(r0, r1, r2, r3, addr)                                            \
    asm volatile("ldmatrix.sync.aligned.m8n8.x4.shared.b16 {%0,%1,%2,%3}, [%4];" \
        : "=r"(r0), "=r"(r1), "=r"(r2), "=r"(r3) : "r"(addr))

#define CP16(dst, src)                                                         \
    asm volatile("cp.async.cg.shared.global [%0], [%1], 16;" :: "r"(dst), "l"(src))
#define CP_COMMIT() asm volatile("cp.async.commit_group;")
#define CP_WAIT(n)  asm volatile("cp.async.wait_group %0;" :: "n"(n))

// ---------------------------------------------------------------------------
// Kernel 1: tensor-core QKV projection, single-pass fp16 x (error budget OK).
// Per CTA: A = x rows [(2h x 64w) = 128 rows x 32c] fp16,
// B = stacked [Wq*PSCALE; Wk; Wv] [96 x 32] fp16.
// grid (512 htiles, 4 b), 256 threads (8 warps x 16 rows).
// ---------------------------------------------------------------------------
#define PXH 0
#define PW  10240
#define PBI 17920
#define PST 0        // output stage overlays PXH/PW after MMAs (64 w x 272B = 17408)
__global__ void __launch_bounds__(256) proj_tc(
    const float* __restrict__ x,
    const float* __restrict__ wq, const float* __restrict__ bq,
    const float* __restrict__ wk, const float* __restrict__ bk,
    const float* __restrict__ wv, const float* __restrict__ bv)
{
    __shared__ __align__(16) char sm[18432];
    const uint32_t sbase = smem_u32(sm);

    const int t = threadIdx.x;
    const int lane = t & 31, warp = t >> 5;
    const int b = blockIdx.y;
    const int h0 = blockIdx.x * 2;

    // ---- W -> smem [o][c] fp16, rows 80B pitch; o: 0-31 q, 32-63 k, 64-95 v
    for (int i = t; i < 3072; i += 256) {
        const int o = i >> 5, c = i & 31;
        float v = (o < 32) ? wq[o * 32 + c] * PSCALE
                : (o < 64) ? wk[(o - 32) * 32 + c]
                           : wv[(o - 64) * 32 + c];
        *(__half*)(sm + PW + o * 80 + c * 2) = __float2half_rn(v);
    }
    if (t < 96) {
        float v = (t < 32) ? bq[t] * PSCALE : (t < 64) ? bk[t - 32] : bv[t - 64];
        *(float*)(sm + PBI + t * 4) = v;
    }

    // ---- x -> smem fp16 [r][c], float-wise: thread owns fixed row r and
    //      16 consecutive channels; pairs packed into u32 stores.
    {
        const int r = t & 127;                 // fixed per thread
        const int cbase = (t >> 7) * 16;       // 0 or 16
        const float* xr = x + ((size_t)(b * 32) * 1024 + h0 + (r >> 6)) * 64 + (r & 63);
        const uint32_t sh = sbase + PXH + r * 80 + cbase * 2;
        #pragma unroll
        for (int k = 0; k < 8; k++) {
            const float f0 = xr[(size_t)(cbase + 2 * k) * 65536];
            const float f1 = xr[(size_t)(cbase + 2 * k + 1) * 65536];
            asm volatile("st.shared.b32 [%0], %1;" :: "r"(sh + k * 4), "r"(pk(f0, f1)));
        }
    }
    __syncthreads();

    // ---- GEMM: 12 n-tiles x (1 LDMX4 + 2 MMA) = 24 MMA/warp
    const int qrow = lane >> 2;
    const int lc4 = (lane & 3) * 4;
    const int wr = warp * 16;

    uint32_t xh[8];
    #pragma unroll
    for (int ks = 0; ks < 2; ks++) {
        const uint32_t aq = sbase + PXH + (wr + qrow) * 80 + lc4 + ks * 32;
        xh[ks * 4 + 0] = lds32(aq);          xh[ks * 4 + 1] = lds32(aq + 640);
        xh[ks * 4 + 2] = lds32(aq + 16);     xh[ks * 4 + 3] = lds32(aq + 656);
    }
    const uint32_t wmoff = (lane & 7) * 80 + ((lane >> 3) & 1) * 16 + (lane >> 4) * 32;

    float acc[12][4];
    #pragma unroll
    for (int nt = 0; nt < 12; nt++) {
        acc[nt][0] = 0.f; acc[nt][1] = 0.f; acc[nt][2] = 0.f; acc[nt][3] = 0.f;
        uint32_t b0, b1, b2, b3;
        LDMX4(b0, b1, b2, b3, sbase + PW + wmoff + nt * 640);
        MMA16816(acc[nt], xh[0], xh[1], xh[2], xh[3], b0, b1);
        MMA16816(acc[nt], xh[4], xh[5], xh[6], xh[7], b2, b3);
    }

    // ---- epilogue: per tensor, stage in smem (272B-pitch rows: 2 hl x 64B)
    //      then write 128B-contiguous per w. Stage addr = w*272 + hl*64 + cb.
    const int r0 = wr + qrow, r1 = r0 + 8;
    const uint32_t st0 = sbase + PST + (r0 & 63) * 272 + (r0 >> 6) * 64;
    const uint32_t st1 = sbase + PST + (r1 & 63) * 272 + (r1 >> 6) * 64;
    #pragma unroll
    for (int tensor = 0; tensor < 3; tensor++) {
        __syncthreads();   // stage region free (A/W-frag reads / prev writeout done)
        #pragma unroll
        for (int j = 0; j < 4; j++) {
            const int nt = tensor * 4 + j;
            const int cb = j * 16 + (lane & 3) * 4;     // byte offset in 64B row
            const float2 bi = *(const float2*)(sm + PBI + tensor * 128 + cb * 2);
            asm volatile("st.shared.b32 [%0], %1;" ::
                "r"(st0 + cb), "r"(pk(acc[nt][0] + bi.x, acc[nt][1] + bi.y)));
            asm volatile("st.shared.b32 [%0], %1;" ::
                "r"(st1 + cb), "r"(pk(acc[nt][2] + bi.x, acc[nt][3] + bi.y)));
        }
        __syncthreads();
        __half* g = (tensor == 0) ? g_Q : (tensor == 1) ? g_K : g_V;
        for (int i = t; i < 512; i += 256) {
            const int w = i >> 3, ch = i & 7;
            *(uint4*)((char*)(g + ((size_t)(b * 64 + w) * 1024 + h0) * 32) + ch * 16) =
                *(const uint4*)(sm + PST + w * 272 + ch * 16);
        }
    }
}

// ---------------------------------------------------------------------------
// Kernel 2: attention (R14-exact). S in two 8-n-tile halves (sacc[8][4],
// 3 CTAs/SM), cp.async triple-buffered K/V, rowsum via ones-column in V pad,
// exp via ex2.f16x2. grid (256, 8), block 256.
// ---------------------------------------------------------------------------
#define SQ    0
#define SKV0  10240
#define SKVSZ 20480
#define ATT_SMEM 71680   // Q 10K + 3 x (K 10K + V 10K); 3 CTAs = 215KB/SM

__global__ void __launch_bounds__(256, 3) att3_kernel(
    const float* __restrict__ w_lin, const float* __restrict__ b_lin)
{
    extern __shared__ char sm[];
    const uint32_t sbase = smem_u32(sm);

    const int t = threadIdx.x;
    const int lane = t & 31, warp = t >> 5;
    const int bw = blockIdx.x, qt = blockIdx.y;

    const int qrow = lane >> 2;
    const int lc4 = (lane & 3) * 4;
    const int wr = warp * 16;

    const size_t qbase = ((size_t)bw * H_ + (size_t)qt * 128) * 32;
    const size_t kvb = (size_t)bw * H_ * 32;

    // ---- ones-column init: V pad bytes (64..79 of each 80B row), 3 buffers.
    for (int row = t; row < 384; row += 256) {
        *(uint4*)(sm + SKV0 + (row >> 7) * SKVSZ + 10240 + (row & 127) * 80 + 64) =
            make_uint4(0x00003C00u, 0u, 0u, 0u);
    }

    // ---- group 0: Q tile + K/V tile 0 (buf 0) ----
    {
        const char* qg = (const char*)(g_Q + qbase);
        const char* kg = (const char*)(g_K + kvb);
        const char* vg = (const char*)(g_V + kvb);
        for (int i = t; i < 512; i += 256) {
            const uint32_t o = (i >> 2) * 80 + (i & 3) * 16;
            CP16(sbase + SQ + o, qg + i * 16);
            CP16(sbase + SKV0 + o, kg + i * 16);
            CP16(sbase + SKV0 + 10240 + o, vg + i * 16);
        }
        CP_COMMIT();
    }

    float sacc[8][4];
    float oacc[5][4];
    #pragma unroll
    for (int n = 0; n < 5; n++)
        #pragma unroll
        for (int e = 0; e < 4; e++) oacc[n][e] = 0.f;

    uint32_t qf[8];   // Q fragments, tile-invariant (loaded once at kt=0)
    // ldmatrix (non-trans) per-lane row address offset for K fragments
    const uint32_t kmoff = (lane & 7) * 80 + ((lane >> 3) & 1) * 16 + (lane >> 4) * 32;

    for (int kt = 0; kt < 8; kt++) {
        if (kt < 7) {   // prefetch next tile into buffer (kt+1)%3
            const char* kg = (const char*)(g_K + kvb + (size_t)(kt + 1) * 4096);
            const char* vg = (const char*)(g_V + kvb + (size_t)(kt + 1) * 4096);
            const uint32_t kb2 = sbase + SKV0 + ((kt + 1) % 3) * SKVSZ;
            for (int i = t; i < 512; i += 256) {
                const uint32_t o = (i >> 2) * 80 + (i & 3) * 16;
                CP16(kb2 + o, kg + i * 16);
                CP16(kb2 + 10240 + o, vg + i * 16);
            }
            CP_COMMIT();
            CP_WAIT(1);
        } else {
            CP_WAIT(0);
        }
        __syncthreads();   // tile kt visible to all warps

        if (kt == 0) {     // Q arrived with group 0 — load frags once
            #pragma unroll
            for (int ks = 0; ks < 2; ks++) {
                const uint32_t aq = sbase + SQ + (wr + qrow) * 80 + lc4 + ks * 32;
                qf[ks * 4 + 0] = lds32(aq);
                qf[ks * 4 + 1] = lds32(aq + 640);
                qf[ks * 4 + 2] = lds32(aq + 16);
                qf[ks * 4 + 3] = lds32(aq + 656);
            }
        }

        const uint32_t kb = sbase + SKV0 + (kt % 3) * SKVSZ;
        const uint32_t vb = kb + 10240;
        const uint32_t kmbase = kb + kmoff;

        // ---- two halves: S for 8 n-tiles, then PV for matching 4 ks ----
        #pragma unroll
        for (int half = 0; half < 2; half++) {
            #pragma unroll
            for (int j = 0; j < 8; j++) {
                sacc[j][0] = 0.f; sacc[j][1] = 0.f; sacc[j][2] = 0.f; sacc[j][3] = 0.f;
                uint32_t b0, b1, b2, b3;
                LDMX4(b0, b1, b2, b3, kmbase + (half * 8 + j) * 640);
                MMA16816(sacc[j], qf[0], qf[1], qf[2], qf[3], b0, b1);
                MMA16816(sacc[j], qf[4], qf[5], qf[6], qf[7], b2, b3);
            }
            #pragma unroll
            for (int k2 = 0; k2 < 4; k2++) {
                const int ks = half * 4 + k2;
                const float* p0 = sacc[2 * k2];
                const float* p1 = sacc[2 * k2 + 1];
                const uint32_t a0 = ex2h2(pk(p0[0], p0[1]));
                const uint32_t a1 = ex2h2(pk(p0[2], p0[3]));
                const uint32_t a2 = ex2h2(pk(p1[0], p1[1]));
                const uint32_t a3 = ex2h2(pk(p1[2], p1[3]));
                const uint32_t va2 = vb + (ks * 16 + (lane & 15)) * 80;
                const uint32_t va4 = va2 + (lane >> 4) * 16;
                uint32_t v0, v1, v2, v3;
                LDMX4T(v0, v1, v2, v3, va4);          // n-tiles 0,1
                MMA16816(oacc[0], a0, a1, a2, a3, v0, v1);
                MMA16816(oacc[1], a0, a1, a2, a3, v2, v3);
                LDMX4T(v0, v1, v2, v3, va4 + 32);     // n-tiles 2,3
                MMA16816(oacc[2], a0, a1, a2, a3, v0, v1);
                MMA16816(oacc[3], a0, a1, a2, a3, v2, v3);
                LDMX2T(v0, v1, va2 + 64);             // ones column (pad bytes)
                MMA16816(oacc[4], a0, a1, a2, a3, v0, v1);
            }
        }
        // no trailing barrier: triple buffer guarantees prefetch (kt+1)%3
        // never aliases any buffer a laggard warp (at worst in compute kt) reads
    }

    // ---- finalize: rowsums live in oacc[4] col ch32 (lane&3==0) ----
    const float rs0 = __shfl_sync(0xffffffffu, oacc[4][0], lane & 28);
    const float rs1 = __shfl_sync(0xffffffffu, oacc[4][2], lane & 28);

    float ws = 0.f;
    #pragma unroll
    for (int k = 0; k < 8; k++) ws += w_lin[k];
    const float bb = b_lin[0];
    const float f0 = ws / rs0, f1 = ws / rs1;

    const int row = qt * 128 + wr + qrow;
    float* ob = g_O + ((size_t)bw * H_ + row) * 32 + (lane & 3) * 2;
    #pragma unroll
    for (int nt = 0; nt < 4; nt++) {
        float2 v0 = make_float2(oacc[nt][0] * f0 + bb, oacc[nt][1] * f0 + bb);
        float2 v1 = make_float2(oacc[nt][2] * f1 + bb, oacc[nt][3] * f1 + bb);
        *(float2*)(ob + nt * 8) = v0;
        *(float2*)(ob + 8 * 32 + nt * 8) = v1;
    }
}

// ---------------------------------------------------------------------------
// Kernel 3: epilogue transpose  g_O [bw][h][c] -> out [b][c][h][w]
// ---------------------------------------------------------------------------
__global__ void __launch_bounds__(256) transpose_kernel(float* __restrict__ out)
{
    __shared__ float tile[32][33];
    const int b = blockIdx.z, h = blockIdx.y, w0 = blockIdx.x * 32;

    for (int wi = threadIdx.y; wi < 32; wi += 8)
        tile[wi][threadIdx.x] = g_O[(((long)(b * 64 + w0 + wi)) * H_ + h) * 32 + threadIdx.x];
    __syncthreads();
    for (int c = threadIdx.y; c < 32; c += 8)
        out[(((long)(b * 32 + c)) * H_ + h) * 64 + w0 + threadIdx.x] = tile[threadIdx.x][c];
}

// ---------------------------------------------------------------------------
extern "C" void kernel_launch(void* const* d_in, const int* in_sizes, int n_in,
                              void* d_out, int out_size)
{
    const float* x  = (const float*)d_in[0];
    const float* wq = (const float*)d_in[1];
    const float* bq = (const float*)d_in[2];
    const float* wk = (const float*)d_in[3];
    const float* bk = (const float*)d_in[4];
    const float* wv = (const float*)d_in[5];
    const float* bv = (const float*)d_in[6];
    const float* wl = (const float*)d_in[7];
    const float* bl = (const float*)d_in[8];
    float* out = (float*)d_out;

    cudaFuncSetAttribute(att3_kernel, cudaFuncAttributeMaxDynamicSharedMemorySize, ATT_SMEM);

    proj_tc<<<dim3(512, 4), 256>>>(x, wq, bq, wk, bk, wv, bv);
    att3_kernel<<<dim3(256, 8), 256, ATT_SMEM>>>(wl, bl);
    transpose_kernel<<<dim3(2, 1024, 4), dim3(32, 8)>>>(out);
}